// round 10
// baseline (speedup 1.0000x reference)
#include <cuda_runtime.h>
#include <stdint.h>

// Problem constants
#define B_   64
#define N_   197
#define C_   768
#define H_   12
#define HD_  64
#define M_   (B_ * N_)     // 12608 rows
#define O3_  (3 * C_)      // 2304 qkv output dim

// Scratch (device globals: allocation-free rule)
__device__ float g_qkv[M_ * O3_];    // [12608, 2304]
__device__ float g_attn[M_ * C_];    // [12608, 768]

// ---------------------------------------------------------------------------
// helpers
// ---------------------------------------------------------------------------
__device__ __forceinline__ void mma_m16n8k8(float c[4], const uint32_t a[4],
                                            uint32_t b0, uint32_t b1) {
    asm volatile(
        "mma.sync.aligned.m16n8k8.row.col.f32.tf32.tf32.f32 "
        "{%0,%1,%2,%3}, {%4,%5,%6,%7}, {%8,%9}, {%0,%1,%2,%3};"
        : "+f"(c[0]), "+f"(c[1]), "+f"(c[2]), "+f"(c[3])
        : "r"(a[0]), "r"(a[1]), "r"(a[2]), "r"(a[3]), "r"(b0), "r"(b1));
}

__device__ __forceinline__ void cp_async16(uint32_t s, const void* g, int srcsz) {
    asm volatile("cp.async.cg.shared.global [%0], [%1], 16, %2;"
                 :: "r"(s), "l"(g), "r"(srcsz));
}
#define CP_COMMIT() asm volatile("cp.async.commit_group;")

// ---------------------------------------------------------------------------
// TF32 GEMM: C[m][n] = sum_k A[m][k] * W[n][k]  (+ bias[n] + resid[m][n])
// A row-major [M,K], W row-major [N,K]. CTA tile 128x128, BK=32, 256 threads.
// THREE-stage cp.async ring, wait_group 1 (2 tiles in flight -> DRAM latency
// hidden behind ~2 tiles of compute). One barrier per k-tile; always-commit
// keeps group accounting exact at the tail. WAR-safe: buffer (kt+2)%3 was
// last read at kt-1, fenced by this iteration's barrier. 2 CTAs/SM.
// ---------------------------------------------------------------------------
template <bool EPI>
__global__ void __launch_bounds__(256, 2) gemm_tf32(
    const float* __restrict__ A, const float* __restrict__ W,
    float* __restrict__ C, int M, int N, int K,
    const float* __restrict__ bias, const float* __restrict__ resid)
{
    extern __shared__ float smem[];
    const int LDT = 36;              // 32 + 4 pad -> conflict-free frag loads
    const int TILE_W = 128 * LDT;    // words per buffer (A x3 then B x3)

    const int tid  = threadIdx.x;
    const int m0   = blockIdx.y * 128;
    const int n0   = blockIdx.x * 128;
    const int warp = tid >> 5, lane = tid & 31;
    const int wm   = (warp & 3) * 32;
    const int wn   = (warp >> 2) * 64;
    const int gp   = lane >> 2, tg = lane & 3;

    const uint32_t smem_u32 = (uint32_t)__cvta_generic_to_shared(smem);

    // per-thread staging descriptors (4 float4 per matrix per tile)
    const float* Ag[4];
    const float* Wg[4];
    int          av[4];
    uint32_t     sa[4], sb[4];
#pragma unroll
    for (int it = 0; it < 4; it++) {
        int f4 = it * 256 + tid;
        int row = f4 >> 3, c4 = (f4 & 7) << 2;
        int gra = m0 + row;
        av[it] = (gra < M) ? 16 : 0;
        Ag[it] = A + (size_t)(gra < M ? gra : 0) * K + c4;
        Wg[it] = W + (size_t)(n0 + row) * K + c4;
        sa[it] = smem_u32 + (uint32_t)(row * LDT + c4) * 4u;
        sb[it] = smem_u32 + (uint32_t)(3 * TILE_W + row * LDT + c4) * 4u;
    }

    float acc[2][8][4];
#pragma unroll
    for (int i = 0; i < 2; i++)
#pragma unroll
        for (int j = 0; j < 8; j++)
#pragma unroll
            for (int k = 0; k < 4; k++) acc[i][j][k] = 0.f;

    const int KT = K >> 5;

    // prologue: tiles 0,1 -> stages 0,1
#pragma unroll
    for (int s = 0; s < 2; s++) {
        int kb = s << 5;
        uint32_t boff = (uint32_t)(s * TILE_W) * 4u;
#pragma unroll
        for (int it = 0; it < 4; it++) {
            cp_async16(sa[it] + boff, Ag[it] + kb, av[it]);
            cp_async16(sb[it] + boff, Wg[it] + kb, 16);
        }
        CP_COMMIT();
    }

    int st = 0;                      // stage of tile kt
    int stp = 2;                     // stage of tile kt+2
    for (int kt = 0; kt < KT; kt++) {
        asm volatile("cp.async.wait_group 1;");   // tile kt landed
        __syncthreads();                           // kt-1 reads of stage stp done

        if (kt + 2 < KT) {
            int kb = (kt + 2) << 5;
            uint32_t boff = (uint32_t)(stp * TILE_W) * 4u;
#pragma unroll
            for (int it = 0; it < 4; it++) {
                cp_async16(sa[it] + boff, Ag[it] + kb, av[it]);
                cp_async16(sb[it] + boff, Wg[it] + kb, 16);
            }
        }
        CP_COMMIT();                 // always: keeps wait_group counts exact

        const uint32_t* Ab = (const uint32_t*)smem + st * TILE_W;
        const uint32_t* Bb = (const uint32_t*)smem + 3 * TILE_W + st * TILE_W;
#pragma unroll
        for (int kk = 0; kk < 4; kk++) {
            int k8 = kk * 8;
            uint32_t af[2][4];
#pragma unroll
            for (int mt = 0; mt < 2; mt++) {
                const uint32_t* ap = Ab + (wm + mt * 16 + gp) * LDT + k8 + tg;
                af[mt][0] = ap[0];
                af[mt][2] = ap[4];
                af[mt][1] = ap[8 * LDT];
                af[mt][3] = ap[8 * LDT + 4];
            }
#pragma unroll
            for (int nt = 0; nt < 8; nt++) {
                const uint32_t* bp = Bb + (wn + nt * 8 + gp) * LDT + k8 + tg;
                uint32_t b0 = bp[0], b1 = bp[4];
                mma_m16n8k8(acc[0][nt], af[0], b0, b1);
                mma_m16n8k8(acc[1][nt], af[1], b0, b1);
            }
        }
        st = (st == 2) ? 0 : st + 1;
        stp = (stp == 2) ? 0 : stp + 1;
    }

    // ---- epilogue ----
#pragma unroll
    for (int mt = 0; mt < 2; mt++) {
#pragma unroll
        for (int nt = 0; nt < 8; nt++) {
            int r0 = m0 + wm + mt * 16 + gp;
            int cc = n0 + wn + nt * 8 + tg * 2;
            if (r0 < M) {
                float2 v = make_float2(acc[mt][nt][0], acc[mt][nt][1]);
                if (EPI) {
                    v.x += bias[cc]     + resid[(size_t)r0 * N + cc];
                    v.y += bias[cc + 1] + resid[(size_t)r0 * N + cc + 1];
                }
                *(float2*)(C + (size_t)r0 * N + cc) = v;
            }
            if (r0 + 8 < M) {
                float2 v = make_float2(acc[mt][nt][2], acc[mt][nt][3]);
                if (EPI) {
                    v.x += bias[cc]     + resid[(size_t)(r0 + 8) * N + cc];
                    v.y += bias[cc + 1] + resid[(size_t)(r0 + 8) * N + cc + 1];
                }
                *(float2*)(C + (size_t)(r0 + 8) * N + cc) = v;
            }
        }
    }
}

// ---------------------------------------------------------------------------
// Fused attention, tf32 MMA, 32-query blocks -> 89.3 KB smem -> 2 CTAs/SM.
// One CTA per (b, h, 32-query block); 512 threads (16 warps, 2 mg x 8 ng).
// Region A (Q[32][68] + K[200][68]) is OVERLAID by VT[64][204] after softmax
// (Q/K dead once S is computed). S kept separately. scale folded into softmax.
//   Q  [32][68]    row-major (raw)                 Q_OFF..
//   K  [200][68]   row-major (rows >=197 zero)     K_OFF..
//   VT [64][204]   d-major (cols >=197 zero)       overlays Q/K
//   S  [32][204]   (cols [197,200) stay 0)
//   inv[32]
// ---------------------------------------------------------------------------
#define QROWS 32
#define NP_   200
#define NT_S  25                           // 200/8 n-tiles for S
#define KLD_  68
#define SLD_  204
#define Q_OFF 0
#define K_OFF (QROWS * KLD_)               // 2176
#define VT_OFF 0                           // overlays Q+K (needs 64*204=13056 <= 15776)
#define S_OFF (K_OFF + NP_ * KLD_)         // 15776
#define I_OFF (S_OFF + QROWS * SLD_)       // 22304
#define ATTN_SMEM_WORDS (I_OFF + QROWS)    // 22336 words = 89344 B

__global__ void __launch_bounds__(512, 2) attn_kernel(const float* __restrict__ scale)
{
    extern __shared__ float sm[];
    float* Q   = sm + Q_OFF;
    float* Kt  = sm + K_OFF;
    float* VT  = sm + VT_OFF;
    float* S   = sm + S_OFF;
    float* inv = sm + I_OFF;

    const int tid = threadIdx.x;
    const int rb = blockIdx.x, h = blockIdx.y, b = blockIdx.z;
    const int base = b * N_;
    const int q0 = rb * QROWS;
    const int Nq = min(QROWS, N_ - q0);
    const float sc = scale[h];

    const int warp = tid >> 5, lane = tid & 31;
    const int gp = lane >> 2, tg = lane & 3;
    const int mg = warp & 1, ng = warp >> 1;   // 2 x 8 warp grid

    const uint32_t smem_u32 = (uint32_t)__cvta_generic_to_shared(sm);

    // ---- async stage Q (raw) and K; zero-fill padded rows ----
    for (int idx = tid; idx < QROWS * 16; idx += 512) {
        int i = idx >> 4, d4 = (idx & 15) << 2;
        const float* src = &g_qkv[(size_t)(base + q0 + (i < Nq ? i : 0)) * O3_ + h * HD_ + d4];
        cp_async16(smem_u32 + (uint32_t)(Q_OFF + i * KLD_ + d4) * 4u, src, i < Nq ? 16 : 0);
    }
    for (int idx = tid; idx < NP_ * 16; idx += 512) {
        int j = idx >> 4, d4 = (idx & 15) << 2;
        const float* src = &g_qkv[(size_t)(base + (j < N_ ? j : 0)) * O3_ + C_ + h * HD_ + d4];
        cp_async16(smem_u32 + (uint32_t)(K_OFF + j * KLD_ + d4) * 4u, src, j < N_ ? 16 : 0);
    }
    CP_COMMIT();
    asm volatile("cp.async.wait_group 0;");
    __syncthreads();

    // ---- S = Q K^T : warp tile m16, tiles t = ng + 8*i (t < 25) ----
    {
        const int wm = mg * 16;
        float acc[4][4];
#pragma unroll
        for (int i = 0; i < 4; i++)
#pragma unroll
            for (int k = 0; k < 4; k++) acc[i][k] = 0.f;

#pragma unroll
        for (int kk = 0; kk < 8; kk++) {
            int k8 = kk * 8;
            uint32_t a[4];
            {
                const uint32_t* ap = (const uint32_t*)Q + (wm + gp) * KLD_ + k8 + tg;
                a[0] = ap[0];
                a[2] = ap[4];
                a[1] = ap[8 * KLD_];
                a[3] = ap[8 * KLD_ + 4];
            }
#pragma unroll
            for (int i = 0; i < 4; i++) {
                int t = ng + 8 * i;
                if (t < NT_S) {
                    const uint32_t* bp = (const uint32_t*)Kt + (t * 8 + gp) * KLD_ + k8 + tg;
                    mma_m16n8k8(acc[i], a, bp[0], bp[4]);
                }
            }
        }
#pragma unroll
        for (int i = 0; i < 4; i++) {
            int t = ng + 8 * i;
            if (t < NT_S) {
                int cc = t * 8 + 2 * tg;
                *(float2*)&S[(wm + gp) * SLD_ + cc]     = make_float2(acc[i][0], acc[i][1]);
                *(float2*)&S[(wm + gp + 8) * SLD_ + cc] = make_float2(acc[i][2], acc[i][3]);
            }
        }
    }
    __syncthreads();   // S done; Q/K dead from here

    // ---- stage V transposed into region A (overlay); loads issued early ----
    for (int idx = tid; idx < NP_ * 16; idx += 512) {
        int j = idx >> 4, d4 = (idx & 15) << 2;
        float4 v = make_float4(0.f, 0.f, 0.f, 0.f);
        if (j < N_)
            v = *(const float4*)&g_qkv[(size_t)(base + j) * O3_ + 2 * C_ + h * HD_ + d4];
        VT[(d4 + 0) * SLD_ + j] = v.x;
        VT[(d4 + 1) * SLD_ + j] = v.y;
        VT[(d4 + 2) * SLD_ + j] = v.z;
        VT[(d4 + 3) * SLD_ + j] = v.w;
    }

    // ---- softmax (16 threads/row); scale folded; diag excluded ----
    {
        int row = tid >> 4, sub = tid & 15;
        float* Sr = &S[row * SLD_];
        int diag = q0 + row;                 // >= N_ for padded rows -> no-op
        float mx = -1e30f;
        for (int j = sub; j < N_; j += 16)
            if (j != diag) mx = fmaxf(mx, sc * Sr[j]);
        mx = fmaxf(mx, __shfl_xor_sync(0xffffffffu, mx, 1));
        mx = fmaxf(mx, __shfl_xor_sync(0xffffffffu, mx, 2));
        mx = fmaxf(mx, __shfl_xor_sync(0xffffffffu, mx, 4));
        mx = fmaxf(mx, __shfl_xor_sync(0xffffffffu, mx, 8));
        float s = 0.f;
        for (int j = sub; j < N_; j += 16) {
            float e = (j == diag) ? 0.f : __expf(sc * Sr[j] - mx);
            Sr[j] = e;
            s += e;
        }
        s += __shfl_xor_sync(0xffffffffu, s, 1);
        s += __shfl_xor_sync(0xffffffffu, s, 2);
        s += __shfl_xor_sync(0xffffffffu, s, 4);
        s += __shfl_xor_sync(0xffffffffu, s, 8);
        if (sub == 0) inv[row] = 1.0f / s;
        // S cols [197,200) stay exactly 0 (zero K pad rows) -> no PV term
    }
    __syncthreads();   // VT staged + P ready

    // ---- O = P V : warp tile m16 x n8, k=200 ----
    {
        const int wm = mg * 16;
        const int wn = ng * 8;               // 8 ng x 8 cols = 64
        float acc[4];
#pragma unroll
        for (int k = 0; k < 4; k++) acc[k] = 0.f;

#pragma unroll 5
        for (int kk = 0; kk < NP_ / 8; kk++) {
            int k8 = kk * 8;
            uint32_t a[4];
            {
                const uint32_t* ap = (const uint32_t*)S + (wm + gp) * SLD_ + k8 + tg;
                a[0] = ap[0];
                a[2] = ap[4];
                a[1] = ap[8 * SLD_];
                a[3] = ap[8 * SLD_ + 4];
            }
            const uint32_t* bp = (const uint32_t*)VT + (wn + gp) * SLD_ + k8 + tg;
            mma_m16n8k8(acc, a, bp[0], bp[4]);
        }
        // epilogue: *= 1/sum, write g_attn
        int cc = h * HD_ + wn + 2 * tg;
        int r0 = wm + gp;
        if (r0 < Nq) {
            float iv = inv[r0];
            *(float2*)&g_attn[(size_t)(base + q0 + r0) * C_ + cc] =
                make_float2(acc[0] * iv, acc[1] * iv);
        }
        if (r0 + 8 < Nq) {
            float iv = inv[r0 + 8];
            *(float2*)&g_attn[(size_t)(base + q0 + r0 + 8) * C_ + cc] =
                make_float2(acc[2] * iv, acc[3] * iv);
        }
    }
}

// ---------------------------------------------------------------------------
// launch
// ---------------------------------------------------------------------------
extern "C" void kernel_launch(void* const* d_in, const int* in_sizes, int n_in,
                              void* d_out, int out_size)
{
    const float* x      = (const float*)d_in[0];
    const float* scale  = (const float*)d_in[1];
    const float* w_qkv  = (const float*)d_in[2];
    const float* w_proj = (const float*)d_in[3];
    const float* b_proj = (const float*)d_in[4];
    float* out = (float*)d_out;

    float *qkv_p, *attn_p;
    cudaGetSymbolAddress((void**)&qkv_p, g_qkv);
    cudaGetSymbolAddress((void**)&attn_p, g_attn);

    const int smem_gemm = 3 * 2 * 128 * 36 * 4;        // 110592 B (3-stage)
    const int smem_attn = ATTN_SMEM_WORDS * 4;         // 89344 B
    cudaFuncSetAttribute(gemm_tf32<false>, cudaFuncAttributeMaxDynamicSharedMemorySize, smem_gemm);
    cudaFuncSetAttribute(gemm_tf32<true>,  cudaFuncAttributeMaxDynamicSharedMemorySize, smem_gemm);
    cudaFuncSetAttribute(attn_kernel,      cudaFuncAttributeMaxDynamicSharedMemorySize, smem_attn);

    // 1) QKV projection: [12608, 2304]
    gemm_tf32<false><<<dim3(O3_ / 128, (M_ + 127) / 128), 256, smem_gemm>>>(
        x, w_qkv, qkv_p, M_, O3_, C_, nullptr, nullptr);

    // 2) fused masked attention per (32-row block, head, batch)
    attn_kernel<<<dim3((N_ + QROWS - 1) / QROWS, H_, B_), 512, smem_attn>>>(scale);

    // 3) output projection + bias + residual
    gemm_tf32<true><<<dim3(C_ / 128, (M_ + 127) / 128), 256, smem_gemm>>>(
        attn_p, w_proj, out, M_, C_, C_, b_proj, x);
}

// round 15
// speedup vs baseline: 1.0800x; 1.0800x over previous
#include <cuda_runtime.h>
#include <stdint.h>

// Problem constants
#define B_   64
#define N_   197
#define C_   768
#define H_   12
#define HD_  64
#define M_   (B_ * N_)     // 12608 rows
#define O3_  (3 * C_)      // 2304 qkv output dim

// Scratch (device globals: allocation-free rule)
__device__ float g_qkv[M_ * O3_];    // [12608, 2304]
__device__ float g_attn[M_ * C_];    // [12608, 768]

// ---------------------------------------------------------------------------
// helpers
// ---------------------------------------------------------------------------
__device__ __forceinline__ void mma_m16n8k8(float c[4], const uint32_t a[4],
                                            uint32_t b0, uint32_t b1) {
    asm volatile(
        "mma.sync.aligned.m16n8k8.row.col.f32.tf32.tf32.f32 "
        "{%0,%1,%2,%3}, {%4,%5,%6,%7}, {%8,%9}, {%0,%1,%2,%3};"
        : "+f"(c[0]), "+f"(c[1]), "+f"(c[2]), "+f"(c[3])
        : "r"(a[0]), "r"(a[1]), "r"(a[2]), "r"(a[3]), "r"(b0), "r"(b1));
}

__device__ __forceinline__ void cp_async16(uint32_t s, const void* g, int srcsz) {
    asm volatile("cp.async.cg.shared.global [%0], [%1], 16, %2;"
                 :: "r"(s), "l"(g), "r"(srcsz));
}
#define CP_COMMIT() asm volatile("cp.async.commit_group;")

// ---------------------------------------------------------------------------
// TF32 GEMM (R9 measured-best): CTA tile 128x128, BK=32, 256 threads,
// TWO-stage cp.async, one barrier per k-tile, 2 CTAs/SM.
// ---------------------------------------------------------------------------
template <bool EPI>
__global__ void __launch_bounds__(256, 2) gemm_tf32(
    const float* __restrict__ A, const float* __restrict__ W,
    float* __restrict__ C, int M, int N, int K,
    const float* __restrict__ bias, const float* __restrict__ resid)
{
    extern __shared__ float smem[];
    const int LDT = 36;              // 32 + 4 pad -> conflict-free frag loads
    const int TILE_W = 128 * LDT;    // words per buffer

    const int tid  = threadIdx.x;
    const int m0   = blockIdx.y * 128;
    const int n0   = blockIdx.x * 128;
    const int warp = tid >> 5, lane = tid & 31;
    const int wm   = (warp & 3) * 32;
    const int wn   = (warp >> 2) * 64;
    const int gp   = lane >> 2, tg = lane & 3;

    const uint32_t smem_u32 = (uint32_t)__cvta_generic_to_shared(smem);

    const float* Ag[4];
    const float* Wg[4];
    int          av[4];
    uint32_t     sa[4], sb[4];
#pragma unroll
    for (int it = 0; it < 4; it++) {
        int f4 = it * 256 + tid;
        int row = f4 >> 3, c4 = (f4 & 7) << 2;
        int gra = m0 + row;
        av[it] = (gra < M) ? 16 : 0;
        Ag[it] = A + (size_t)(gra < M ? gra : 0) * K + c4;
        Wg[it] = W + (size_t)(n0 + row) * K + c4;
        sa[it] = smem_u32 + (uint32_t)(row * LDT + c4) * 4u;
        sb[it] = smem_u32 + (uint32_t)(2 * TILE_W + row * LDT + c4) * 4u;
    }

    float acc[2][8][4];
#pragma unroll
    for (int i = 0; i < 2; i++)
#pragma unroll
        for (int j = 0; j < 8; j++)
#pragma unroll
            for (int k = 0; k < 4; k++) acc[i][j][k] = 0.f;

    const int KT = K >> 5;

    // prologue: tile 0 -> buffer 0
#pragma unroll
    for (int it = 0; it < 4; it++) {
        cp_async16(sa[it], Ag[it], av[it]);
        cp_async16(sb[it], Wg[it], 16);
    }
    CP_COMMIT();

    for (int kt = 0; kt < KT; kt++) {
        asm volatile("cp.async.wait_group 0;");   // tile kt landed
        __syncthreads();                           // visible; kt-1 reads done

        if (kt + 1 < KT) {                        // prefetch kt+1 during compute
            int kb = (kt + 1) << 5;
            uint32_t boff = (uint32_t)(((kt + 1) & 1) * TILE_W) * 4u;
#pragma unroll
            for (int it = 0; it < 4; it++) {
                cp_async16(sa[it] + boff, Ag[it] + kb, av[it]);
                cp_async16(sb[it] + boff, Wg[it] + kb, 16);
            }
            CP_COMMIT();
        }

        const uint32_t* Ab = (const uint32_t*)smem + (kt & 1) * TILE_W;
        const uint32_t* Bb = (const uint32_t*)smem + 2 * TILE_W + (kt & 1) * TILE_W;
#pragma unroll
        for (int kk = 0; kk < 4; kk++) {
            int k8 = kk * 8;
            uint32_t af[2][4];
#pragma unroll
            for (int mt = 0; mt < 2; mt++) {
                const uint32_t* ap = Ab + (wm + mt * 16 + gp) * LDT + k8 + tg;
                af[mt][0] = ap[0];
                af[mt][2] = ap[4];
                af[mt][1] = ap[8 * LDT];
                af[mt][3] = ap[8 * LDT + 4];
            }
#pragma unroll
            for (int nt = 0; nt < 8; nt++) {
                const uint32_t* bp = Bb + (wn + nt * 8 + gp) * LDT + k8 + tg;
                uint32_t b0 = bp[0], b1 = bp[4];
                mma_m16n8k8(acc[0][nt], af[0], b0, b1);
                mma_m16n8k8(acc[1][nt], af[1], b0, b1);
            }
        }
    }

    // ---- epilogue ----
#pragma unroll
    for (int mt = 0; mt < 2; mt++) {
#pragma unroll
        for (int nt = 0; nt < 8; nt++) {
            int r0 = m0 + wm + mt * 16 + gp;
            int cc = n0 + wn + nt * 8 + tg * 2;
            if (r0 < M) {
                float2 v = make_float2(acc[mt][nt][0], acc[mt][nt][1]);
                if (EPI) {
                    v.x += bias[cc]     + resid[(size_t)r0 * N + cc];
                    v.y += bias[cc + 1] + resid[(size_t)r0 * N + cc + 1];
                }
                *(float2*)(C + (size_t)r0 * N + cc) = v;
            }
            if (r0 + 8 < M) {
                float2 v = make_float2(acc[mt][nt][2], acc[mt][nt][3]);
                if (EPI) {
                    v.x += bias[cc]     + resid[(size_t)(r0 + 8) * N + cc];
                    v.y += bias[cc + 1] + resid[(size_t)(r0 + 8) * N + cc + 1];
                }
                *(float2*)(C + (size_t)(r0 + 8) * N + cc) = v;
            }
        }
    }
}

// ---------------------------------------------------------------------------
// Fused attention v3 (fixed): one CTA per (b, h). K/V staged ONCE, loop over
// seven 32-query blocks with double-buffered Q prefetch. 512 threads.
//   K  [200][68]  row-major (rows >=197 zero)
//   VT [64][204]  d-major   (cols >=197 zero)
//   Q  [2][32][68] double buffer (raw)
//   S  [32][204]  (cols [197,200) stay 0)
//   inv[32]
// 150.3 KB smem -> 1 CTA/SM; K/V latency amortized over 7 blocks.
// FIX vs R14: prefetch cp.async destination now includes smem_u32 base
// (was a raw byte offset -> writes landed outside the intended Q buffer).
// ---------------------------------------------------------------------------
#define QROWS 32
#define NQB   ((N_ + QROWS - 1) / QROWS)   // 7 query blocks
#define NP_   200
#define NT_S  25                           // 200/8 n-tiles for S
#define KLD_  68
#define SLD_  204
#define K_OFF   0
#define VT_OFF  (NP_ * KLD_)               // 13600
#define Q_OFF   (VT_OFF + 64 * SLD_)       // 26656
#define QBUF_W  (QROWS * KLD_)             // 2176 words per Q buffer
#define S_OFF   (Q_OFF + 2 * QBUF_W)       // 31008
#define I_OFF   (S_OFF + QROWS * SLD_)     // 37536
#define ATTN_SMEM_WORDS (I_OFF + QROWS)    // 37568 words = 150272 B

__global__ void __launch_bounds__(512) attn_kernel(const float* __restrict__ scale)
{
    extern __shared__ float sm[];
    float* Kt  = sm + K_OFF;
    float* VT  = sm + VT_OFF;
    float* S   = sm + S_OFF;
    float* inv = sm + I_OFF;

    const int tid = threadIdx.x;
    const int h = blockIdx.x, b = blockIdx.y;
    const int base = b * N_;
    const float sc = scale[h];

    const int warp = tid >> 5, lane = tid & 31;
    const int gp = lane >> 2, tg = lane & 3;
    const int mg = warp & 1, ng = warp >> 1;   // 2 x 8 warp grid

    const uint32_t smem_u32 = (uint32_t)__cvta_generic_to_shared(sm);

    // ---- stage K via cp.async (zero-fill pad rows) ----
    for (int idx = tid; idx < NP_ * 16; idx += 512) {
        int j = idx >> 4, d4 = (idx & 15) << 2;
        const float* src = &g_qkv[(size_t)(base + (j < N_ ? j : 0)) * O3_ + C_ + h * HD_ + d4];
        cp_async16(smem_u32 + (uint32_t)(K_OFF + j * KLD_ + d4) * 4u, src, j < N_ ? 16 : 0);
    }
    // ---- stage Q block 0 via cp.async ----
    for (int idx = tid; idx < QROWS * 16; idx += 512) {
        int i = idx >> 4, d4 = (idx & 15) << 2;
        cp_async16(smem_u32 + (uint32_t)(Q_OFF + i * KLD_ + d4) * 4u,
                   &g_qkv[(size_t)(base + i) * O3_ + h * HD_ + d4], 16);
    }
    CP_COMMIT();

    // ---- stage V transposed (manual; overlaps with cp.async above) ----
    for (int idx = tid; idx < NP_ * 16; idx += 512) {
        int j = idx >> 4, d4 = (idx & 15) << 2;
        float4 v = make_float4(0.f, 0.f, 0.f, 0.f);
        if (j < N_)
            v = *(const float4*)&g_qkv[(size_t)(base + j) * O3_ + 2 * C_ + h * HD_ + d4];
        VT[(d4 + 0) * SLD_ + j] = v.x;
        VT[(d4 + 1) * SLD_ + j] = v.y;
        VT[(d4 + 2) * SLD_ + j] = v.z;
        VT[(d4 + 3) * SLD_ + j] = v.w;
    }
    asm volatile("cp.async.wait_group 0;");
    __syncthreads();

    // ==== loop over query blocks ====
    for (int qb = 0; qb < NQB; qb++) {
        const int q0 = qb * QROWS;
        const int Nq = min(QROWS, N_ - q0);
        const float* Q = sm + Q_OFF + (qb & 1) * QBUF_W;

        // prefetch next Q block into the other buffer (WAR-safe: that buffer's
        // last reader was block qb-1's S phase, fenced by the end-of-loop sync)
        if (qb + 1 < NQB) {
            int p0 = (qb + 1) * QROWS;
            int Np = N_ - p0;
            uint32_t bofs = smem_u32 +
                (uint32_t)(Q_OFF + ((qb + 1) & 1) * QBUF_W) * 4u;   // FIX: + smem_u32
            for (int idx = tid; idx < QROWS * 16; idx += 512) {
                int i = idx >> 4, d4 = (idx & 15) << 2;
                const float* src =
                    &g_qkv[(size_t)(base + p0 + (i < Np ? i : 0)) * O3_ + h * HD_ + d4];
                cp_async16(bofs + (uint32_t)(i * KLD_ + d4) * 4u, src, i < Np ? 16 : 0);
            }
        }
        CP_COMMIT();

        // ---- S = Q K^T : warp tile m16, tiles t = ng + 8*i (t < 25) ----
        {
            const int wm = mg * 16;
            float acc[4][4];
#pragma unroll
            for (int i = 0; i < 4; i++)
#pragma unroll
                for (int k = 0; k < 4; k++) acc[i][k] = 0.f;

#pragma unroll
            for (int kk = 0; kk < 8; kk++) {
                int k8 = kk * 8;
                uint32_t a[4];
                {
                    const uint32_t* ap = (const uint32_t*)Q + (wm + gp) * KLD_ + k8 + tg;
                    a[0] = ap[0];
                    a[2] = ap[4];
                    a[1] = ap[8 * KLD_];
                    a[3] = ap[8 * KLD_ + 4];
                }
#pragma unroll
                for (int i = 0; i < 4; i++) {
                    int t = ng + 8 * i;
                    if (t < NT_S) {
                        const uint32_t* bp = (const uint32_t*)Kt + (t * 8 + gp) * KLD_ + k8 + tg;
                        mma_m16n8k8(acc[i], a, bp[0], bp[4]);
                    }
                }
            }
#pragma unroll
            for (int i = 0; i < 4; i++) {
                int t = ng + 8 * i;
                if (t < NT_S) {
                    int cc = t * 8 + 2 * tg;
                    *(float2*)&S[(wm + gp) * SLD_ + cc]     = make_float2(acc[i][0], acc[i][1]);
                    *(float2*)&S[(wm + gp + 8) * SLD_ + cc] = make_float2(acc[i][2], acc[i][3]);
                }
            }
        }
        __syncthreads();

        // ---- softmax (16 threads/row); scale folded; diag excluded ----
        {
            int row = tid >> 4, sub = tid & 15;
            float* Sr = &S[row * SLD_];
            int diag = q0 + row;             // >= N_ for padded rows -> no-op
            float mx = -1e30f;
            for (int j = sub; j < N_; j += 16)
                if (j != diag) mx = fmaxf(mx, sc * Sr[j]);
            mx = fmaxf(mx, __shfl_xor_sync(0xffffffffu, mx, 1));
            mx = fmaxf(mx, __shfl_xor_sync(0xffffffffu, mx, 2));
            mx = fmaxf(mx, __shfl_xor_sync(0xffffffffu, mx, 4));
            mx = fmaxf(mx, __shfl_xor_sync(0xffffffffu, mx, 8));
            float s = 0.f;
            for (int j = sub; j < N_; j += 16) {
                float e = (j == diag) ? 0.f : __expf(sc * Sr[j] - mx);
                Sr[j] = e;
                s += e;
            }
            s += __shfl_xor_sync(0xffffffffu, s, 1);
            s += __shfl_xor_sync(0xffffffffu, s, 2);
            s += __shfl_xor_sync(0xffffffffu, s, 4);
            s += __shfl_xor_sync(0xffffffffu, s, 8);
            if (sub == 0) inv[row] = 1.0f / s;
            // S cols [197,200) stay exactly 0 (zero K pad rows) -> no PV term
        }
        __syncthreads();

        // ---- O = P V : warp tile m16 x n8, k=200 ----
        {
            const int wm = mg * 16;
            const int wn = ng * 8;           // 8 ng x 8 cols = 64
            float acc[4];
#pragma unroll
            for (int k = 0; k < 4; k++) acc[k] = 0.f;

#pragma unroll 5
            for (int kk = 0; kk < NP_ / 8; kk++) {
                int k8 = kk * 8;
                uint32_t a[4];
                {
                    const uint32_t* ap = (const uint32_t*)S + (wm + gp) * SLD_ + k8 + tg;
                    a[0] = ap[0];
                    a[2] = ap[4];
                    a[1] = ap[8 * SLD_];
                    a[3] = ap[8 * SLD_ + 4];
                }
                const uint32_t* bp = (const uint32_t*)VT + (wn + gp) * SLD_ + k8 + tg;
                mma_m16n8k8(acc, a, bp[0], bp[4]);
            }
            int cc = h * HD_ + wn + 2 * tg;
            int r0 = wm + gp;
            if (r0 < Nq) {
                float iv = inv[r0];
                *(float2*)&g_attn[(size_t)(base + q0 + r0) * C_ + cc] =
                    make_float2(acc[0] * iv, acc[1] * iv);
            }
            if (r0 + 8 < Nq) {
                float iv = inv[r0 + 8];
                *(float2*)&g_attn[(size_t)(base + q0 + r0 + 8) * C_ + cc] =
                    make_float2(acc[2] * iv, acc[3] * iv);
            }
        }

        // Q prefetch landed; fence S/Q reuse for next block
        asm volatile("cp.async.wait_group 0;");
        __syncthreads();
    }
}

// ---------------------------------------------------------------------------
// launch
// ---------------------------------------------------------------------------
extern "C" void kernel_launch(void* const* d_in, const int* in_sizes, int n_in,
                              void* d_out, int out_size)
{
    const float* x      = (const float*)d_in[0];
    const float* scale  = (const float*)d_in[1];
    const float* w_qkv  = (const float*)d_in[2];
    const float* w_proj = (const float*)d_in[3];
    const float* b_proj = (const float*)d_in[4];
    float* out = (float*)d_out;

    float *qkv_p, *attn_p;
    cudaGetSymbolAddress((void**)&qkv_p, g_qkv);
    cudaGetSymbolAddress((void**)&attn_p, g_attn);

    const int smem_gemm = 2 * 2 * 128 * 36 * 4;        // 73728 B (2-stage, R9-best)
    const int smem_attn = ATTN_SMEM_WORDS * 4;         // 150272 B
    cudaFuncSetAttribute(gemm_tf32<false>, cudaFuncAttributeMaxDynamicSharedMemorySize, smem_gemm);
    cudaFuncSetAttribute(gemm_tf32<true>,  cudaFuncAttributeMaxDynamicSharedMemorySize, smem_gemm);
    cudaFuncSetAttribute(attn_kernel,      cudaFuncAttributeMaxDynamicSharedMemorySize, smem_attn);

    // 1) QKV projection: [12608, 2304]
    gemm_tf32<false><<<dim3(O3_ / 128, (M_ + 127) / 128), 256, smem_gemm>>>(
        x, w_qkv, qkv_p, M_, O3_, C_, nullptr, nullptr);

    // 2) fused masked attention: one CTA per (head, batch)
    attn_kernel<<<dim3(H_, B_), 512, smem_attn>>>(scale);

    // 3) output projection + bias + residual
    gemm_tf32<true><<<dim3(C_ / 128, (M_ + 127) / 128), 256, smem_gemm>>>(
        attn_p, w_proj, out, M_, C_, C_, b_proj, x);
}

// round 17
// speedup vs baseline: 1.4614x; 1.3531x over previous
#include <cuda_runtime.h>
#include <cuda_bf16.h>
#include <stdint.h>

// Problem constants
#define B_   64
#define N_   197
#define C_   768
#define H_   12
#define HD_  64
#define M_   (B_ * N_)     // 12608 rows
#define O3_  (3 * C_)      // 2304 qkv output dim

// Scratch (device globals: allocation-free rule)
__device__ float          g_qkv[M_ * O3_];        // fp32 [12608, 2304] (attn reads fp32)
__device__ __nv_bfloat16  g_attn_bf[M_ * C_];     // bf16 [12608, 768]  (gemm2 A)
__device__ __nv_bfloat16  g_x_bf[M_ * C_];        // bf16 x             (gemm1 A)
__device__ __nv_bfloat16  g_wqkv_bf[O3_ * C_];    // bf16 w_qkv         (gemm1 W)
__device__ __nv_bfloat16  g_wproj_bf[C_ * C_];    // bf16 w_proj        (gemm2 W)

// ---------------------------------------------------------------------------
// helpers
// ---------------------------------------------------------------------------
__device__ __forceinline__ void mma_m16n8k8(float c[4], const uint32_t a[4],
                                            uint32_t b0, uint32_t b1) {
    asm volatile(
        "mma.sync.aligned.m16n8k8.row.col.f32.tf32.tf32.f32 "
        "{%0,%1,%2,%3}, {%4,%5,%6,%7}, {%8,%9}, {%0,%1,%2,%3};"
        : "+f"(c[0]), "+f"(c[1]), "+f"(c[2]), "+f"(c[3])
        : "r"(a[0]), "r"(a[1]), "r"(a[2]), "r"(a[3]), "r"(b0), "r"(b1));
}

__device__ __forceinline__ void mma_bf16_m16n8k16(float c[4], const uint32_t a[4],
                                                  uint32_t b0, uint32_t b1) {
    asm volatile(
        "mma.sync.aligned.m16n8k16.row.col.f32.bf16.bf16.f32 "
        "{%0,%1,%2,%3}, {%4,%5,%6,%7}, {%8,%9}, {%0,%1,%2,%3};"
        : "+f"(c[0]), "+f"(c[1]), "+f"(c[2]), "+f"(c[3])
        : "r"(a[0]), "r"(a[1]), "r"(a[2]), "r"(a[3]), "r"(b0), "r"(b1));
}

__device__ __forceinline__ void cp_async16(uint32_t s, const void* g, int srcsz) {
    asm volatile("cp.async.cg.shared.global [%0], [%1], 16, %2;"
                 :: "r"(s), "l"(g), "r"(srcsz));
}
#define CP_COMMIT() asm volatile("cp.async.commit_group;")

// ---------------------------------------------------------------------------
// fp32 -> bf16 elementwise convert (vectorized float4 -> 4x bf16)
// ---------------------------------------------------------------------------
__global__ void __launch_bounds__(256) cvt_bf16(const float4* __restrict__ src,
                                                uint2* __restrict__ dst, int n4)
{
    int i = blockIdx.x * 256 + threadIdx.x;
    if (i < n4) {
        float4 v = src[i];
        __nv_bfloat162 lo = __floats2bfloat162_rn(v.x, v.y);
        __nv_bfloat162 hi = __floats2bfloat162_rn(v.z, v.w);
        uint2 o;
        o.x = *(uint32_t*)&lo;
        o.y = *(uint32_t*)&hi;
        dst[i] = o;
    }
}

// ---------------------------------------------------------------------------
// BF16 GEMM: C[m][n] = sum_k A[m][k]*W[n][k] (+ bias[n] + resid[m][n])
// A bf16 [M,K], W bf16 [N,K] row-major (k contiguous). CTA tile 128x128,
// BK=64 bf16 (128 B/row, same 73.7 KB smem as the tf32 version), 256 thr,
// two-stage cp.async, one barrier per k-tile, 2 CTAs/SM.
// Word-unit fragment addressing is IDENTICAL to the proven tf32 m16n8k8
// loop (a-words tg/tg+4 on rows gp/gp+8; b-words tg/tg+4), k16 per mma.
// ---------------------------------------------------------------------------
template <bool EPI>
__global__ void __launch_bounds__(256, 2) gemm_bf16(
    const __nv_bfloat16* __restrict__ A, const __nv_bfloat16* __restrict__ W,
    float* __restrict__ C, int M, int N, int K,
    const float* __restrict__ bias, const float* __restrict__ resid)
{
    extern __shared__ uint32_t smem[];       // word-addressed
    const int LDT = 36;              // 32 k-words (64 bf16) + 4 pad
    const int TILE_W = 128 * LDT;    // words per buffer

    const int tid  = threadIdx.x;
    const int m0   = blockIdx.y * 128;
    const int n0   = blockIdx.x * 128;
    const int warp = tid >> 5, lane = tid & 31;
    const int wm   = (warp & 3) * 32;
    const int wn   = (warp >> 2) * 64;
    const int gp   = lane >> 2, tg = lane & 3;

    const uint32_t smem_u32 = (uint32_t)__cvta_generic_to_shared(smem);

    // staging: 128 rows x 8 chunks(16B) per matrix = 1024 = 4 per thread
    const __nv_bfloat16* Ag[4];
    const __nv_bfloat16* Wg[4];
    int          av[4];
    uint32_t     sa[4], sb[4];
#pragma unroll
    for (int it = 0; it < 4; it++) {
        int f4 = it * 256 + tid;
        int row = f4 >> 3, c8 = (f4 & 7) * 8;       // 8 bf16 per 16B chunk
        int gra = m0 + row;
        av[it] = (gra < M) ? 16 : 0;
        Ag[it] = A + (size_t)(gra < M ? gra : 0) * K + c8;
        Wg[it] = W + (size_t)(n0 + row) * K + c8;
        uint32_t w4 = (uint32_t)(row * LDT + (f4 & 7) * 4);   // 4 words = 16B
        sa[it] = smem_u32 + w4 * 4u;
        sb[it] = smem_u32 + (uint32_t)(2 * TILE_W) * 4u + w4 * 4u;
    }

    float acc[2][8][4];
#pragma unroll
    for (int i = 0; i < 2; i++)
#pragma unroll
        for (int j = 0; j < 8; j++)
#pragma unroll
            for (int k = 0; k < 4; k++) acc[i][j][k] = 0.f;

    const int KT = K >> 6;                   // BK = 64 bf16

    // prologue: tile 0 -> buffer 0
#pragma unroll
    for (int it = 0; it < 4; it++) {
        cp_async16(sa[it], Ag[it], av[it]);
        cp_async16(sb[it], Wg[it], 16);
    }
    CP_COMMIT();

    for (int kt = 0; kt < KT; kt++) {
        asm volatile("cp.async.wait_group 0;");   // tile kt landed
        __syncthreads();                           // kt-1 reads done

        if (kt + 1 < KT) {
            int kb = (kt + 1) << 6;               // 64 bf16 per tile
            uint32_t boff = (uint32_t)(((kt + 1) & 1) * TILE_W) * 4u;
#pragma unroll
            for (int it = 0; it < 4; it++) {
                cp_async16(sa[it] + boff, Ag[it] + kb, av[it]);
                cp_async16(sb[it] + boff, Wg[it] + kb, 16);
            }
            CP_COMMIT();
        }

        const uint32_t* Ab = smem + (kt & 1) * TILE_W;
        const uint32_t* Bb = smem + 2 * TILE_W + (kt & 1) * TILE_W;
#pragma unroll
        for (int kk = 0; kk < 4; kk++) {          // 4 x k16 = 64
            int k8 = kk * 8;                      // word offset
            uint32_t af[2][4];
#pragma unroll
            for (int mt = 0; mt < 2; mt++) {
                const uint32_t* ap = Ab + (wm + mt * 16 + gp) * LDT + k8 + tg;
                af[mt][0] = ap[0];
                af[mt][2] = ap[4];
                af[mt][1] = ap[8 * LDT];
                af[mt][3] = ap[8 * LDT + 4];
            }
#pragma unroll
            for (int nt = 0; nt < 8; nt++) {
                const uint32_t* bp = Bb + (wn + nt * 8 + gp) * LDT + k8 + tg;
                uint32_t b0 = bp[0], b1 = bp[4];
                mma_bf16_m16n8k16(acc[0][nt], af[0], b0, b1);
                mma_bf16_m16n8k16(acc[1][nt], af[1], b0, b1);
            }
        }
    }

    // ---- epilogue (same m16n8 acc layout as tf32) ----
#pragma unroll
    for (int mt = 0; mt < 2; mt++) {
#pragma unroll
        for (int nt = 0; nt < 8; nt++) {
            int r0 = m0 + wm + mt * 16 + gp;
            int cc = n0 + wn + nt * 8 + tg * 2;
            if (r0 < M) {
                float2 v = make_float2(acc[mt][nt][0], acc[mt][nt][1]);
                if (EPI) {
                    v.x += bias[cc]     + resid[(size_t)r0 * N + cc];
                    v.y += bias[cc + 1] + resid[(size_t)r0 * N + cc + 1];
                }
                *(float2*)(C + (size_t)r0 * N + cc) = v;
            }
            if (r0 + 8 < M) {
                float2 v = make_float2(acc[mt][nt][2], acc[mt][nt][3]);
                if (EPI) {
                    v.x += bias[cc]     + resid[(size_t)(r0 + 8) * N + cc];
                    v.y += bias[cc + 1] + resid[(size_t)(r0 + 8) * N + cc + 1];
                }
                *(float2*)(C + (size_t)(r0 + 8) * N + cc) = v;
            }
        }
    }
}

// ---------------------------------------------------------------------------
// Fused attention v3 (R15-passing, unchanged math): one CTA per (b, h).
// K/V staged once; 7x 32-query blocks, double-buffered Q prefetch; tf32 MMA.
// ONLY change: epilogue writes bf16 into g_attn_bf (gemm2 input).
// ---------------------------------------------------------------------------
#define QROWS 32
#define NQB   ((N_ + QROWS - 1) / QROWS)   // 7 query blocks
#define NP_   200
#define NT_S  25                           // 200/8 n-tiles for S
#define KLD_  68
#define SLD_  204
#define K_OFF   0
#define VT_OFF  (NP_ * KLD_)               // 13600
#define Q_OFF   (VT_OFF + 64 * SLD_)       // 26656
#define QBUF_W  (QROWS * KLD_)             // 2176 words per Q buffer
#define S_OFF   (Q_OFF + 2 * QBUF_W)       // 31008
#define I_OFF   (S_OFF + QROWS * SLD_)     // 37536
#define ATTN_SMEM_WORDS (I_OFF + QROWS)    // 37568 words = 150272 B

__global__ void __launch_bounds__(512) attn_kernel(const float* __restrict__ scale)
{
    extern __shared__ float sm[];
    float* Kt  = sm + K_OFF;
    float* VT  = sm + VT_OFF;
    float* S   = sm + S_OFF;
    float* inv = sm + I_OFF;

    const int tid = threadIdx.x;
    const int h = blockIdx.x, b = blockIdx.y;
    const int base = b * N_;
    const float sc = scale[h];

    const int warp = tid >> 5, lane = tid & 31;
    const int gp = lane >> 2, tg = lane & 3;
    const int mg = warp & 1, ng = warp >> 1;   // 2 x 8 warp grid

    const uint32_t smem_u32 = (uint32_t)__cvta_generic_to_shared(sm);

    // ---- stage K via cp.async (zero-fill pad rows) ----
    for (int idx = tid; idx < NP_ * 16; idx += 512) {
        int j = idx >> 4, d4 = (idx & 15) << 2;
        const float* src = &g_qkv[(size_t)(base + (j < N_ ? j : 0)) * O3_ + C_ + h * HD_ + d4];
        cp_async16(smem_u32 + (uint32_t)(K_OFF + j * KLD_ + d4) * 4u, src, j < N_ ? 16 : 0);
    }
    // ---- stage Q block 0 via cp.async ----
    for (int idx = tid; idx < QROWS * 16; idx += 512) {
        int i = idx >> 4, d4 = (idx & 15) << 2;
        cp_async16(smem_u32 + (uint32_t)(Q_OFF + i * KLD_ + d4) * 4u,
                   &g_qkv[(size_t)(base + i) * O3_ + h * HD_ + d4], 16);
    }
    CP_COMMIT();

    // ---- stage V transposed (manual; overlaps with cp.async above) ----
    for (int idx = tid; idx < NP_ * 16; idx += 512) {
        int j = idx >> 4, d4 = (idx & 15) << 2;
        float4 v = make_float4(0.f, 0.f, 0.f, 0.f);
        if (j < N_)
            v = *(const float4*)&g_qkv[(size_t)(base + j) * O3_ + 2 * C_ + h * HD_ + d4];
        VT[(d4 + 0) * SLD_ + j] = v.x;
        VT[(d4 + 1) * SLD_ + j] = v.y;
        VT[(d4 + 2) * SLD_ + j] = v.z;
        VT[(d4 + 3) * SLD_ + j] = v.w;
    }
    asm volatile("cp.async.wait_group 0;");
    __syncthreads();

    // ==== loop over query blocks ====
    for (int qb = 0; qb < NQB; qb++) {
        const int q0 = qb * QROWS;
        const int Nq = min(QROWS, N_ - q0);
        const float* Q = sm + Q_OFF + (qb & 1) * QBUF_W;

        // prefetch next Q block into the other buffer
        if (qb + 1 < NQB) {
            int p0 = (qb + 1) * QROWS;
            int Np = N_ - p0;
            uint32_t bofs = smem_u32 +
                (uint32_t)(Q_OFF + ((qb + 1) & 1) * QBUF_W) * 4u;
            for (int idx = tid; idx < QROWS * 16; idx += 512) {
                int i = idx >> 4, d4 = (idx & 15) << 2;
                const float* src =
                    &g_qkv[(size_t)(base + p0 + (i < Np ? i : 0)) * O3_ + h * HD_ + d4];
                cp_async16(bofs + (uint32_t)(i * KLD_ + d4) * 4u, src, i < Np ? 16 : 0);
            }
        }
        CP_COMMIT();

        // ---- S = Q K^T : warp tile m16, tiles t = ng + 8*i (t < 25) ----
        {
            const int wm = mg * 16;
            float acc[4][4];
#pragma unroll
            for (int i = 0; i < 4; i++)
#pragma unroll
                for (int k = 0; k < 4; k++) acc[i][k] = 0.f;

#pragma unroll
            for (int kk = 0; kk < 8; kk++) {
                int k8 = kk * 8;
                uint32_t a[4];
                {
                    const uint32_t* ap = (const uint32_t*)Q + (wm + gp) * KLD_ + k8 + tg;
                    a[0] = ap[0];
                    a[2] = ap[4];
                    a[1] = ap[8 * KLD_];
                    a[3] = ap[8 * KLD_ + 4];
                }
#pragma unroll
                for (int i = 0; i < 4; i++) {
                    int t = ng + 8 * i;
                    if (t < NT_S) {
                        const uint32_t* bp = (const uint32_t*)Kt + (t * 8 + gp) * KLD_ + k8 + tg;
                        mma_m16n8k8(acc[i], a, bp[0], bp[4]);
                    }
                }
            }
#pragma unroll
            for (int i = 0; i < 4; i++) {
                int t = ng + 8 * i;
                if (t < NT_S) {
                    int cc = t * 8 + 2 * tg;
                    *(float2*)&S[(wm + gp) * SLD_ + cc]     = make_float2(acc[i][0], acc[i][1]);
                    *(float2*)&S[(wm + gp + 8) * SLD_ + cc] = make_float2(acc[i][2], acc[i][3]);
                }
            }
        }
        __syncthreads();

        // ---- softmax (16 threads/row); scale folded; diag excluded ----
        {
            int row = tid >> 4, sub = tid & 15;
            float* Sr = &S[row * SLD_];
            int diag = q0 + row;             // >= N_ for padded rows -> no-op
            float mx = -1e30f;
            for (int j = sub; j < N_; j += 16)
                if (j != diag) mx = fmaxf(mx, sc * Sr[j]);
            mx = fmaxf(mx, __shfl_xor_sync(0xffffffffu, mx, 1));
            mx = fmaxf(mx, __shfl_xor_sync(0xffffffffu, mx, 2));
            mx = fmaxf(mx, __shfl_xor_sync(0xffffffffu, mx, 4));
            mx = fmaxf(mx, __shfl_xor_sync(0xffffffffu, mx, 8));
            float s = 0.f;
            for (int j = sub; j < N_; j += 16) {
                float e = (j == diag) ? 0.f : __expf(sc * Sr[j] - mx);
                Sr[j] = e;
                s += e;
            }
            s += __shfl_xor_sync(0xffffffffu, s, 1);
            s += __shfl_xor_sync(0xffffffffu, s, 2);
            s += __shfl_xor_sync(0xffffffffu, s, 4);
            s += __shfl_xor_sync(0xffffffffu, s, 8);
            if (sub == 0) inv[row] = 1.0f / s;
            // S cols [197,200) stay exactly 0 (zero K pad rows) -> no PV term
        }
        __syncthreads();

        // ---- O = P V : warp tile m16 x n8, k=200; write bf16 ----
        {
            const int wm = mg * 16;
            const int wn = ng * 8;           // 8 ng x 8 cols = 64
            float acc[4];
#pragma unroll
            for (int k = 0; k < 4; k++) acc[k] = 0.f;

#pragma unroll 5
            for (int kk = 0; kk < NP_ / 8; kk++) {
                int k8 = kk * 8;
                uint32_t a[4];
                {
                    const uint32_t* ap = (const uint32_t*)S + (wm + gp) * SLD_ + k8 + tg;
                    a[0] = ap[0];
                    a[2] = ap[4];
                    a[1] = ap[8 * SLD_];
                    a[3] = ap[8 * SLD_ + 4];
                }
                const uint32_t* bp = (const uint32_t*)VT + (wn + gp) * SLD_ + k8 + tg;
                mma_m16n8k8(acc, a, bp[0], bp[4]);
            }
            int cc = h * HD_ + wn + 2 * tg;
            int r0 = wm + gp;
            if (r0 < Nq) {
                float iv = inv[r0];
                __nv_bfloat162 o = __floats2bfloat162_rn(acc[0] * iv, acc[1] * iv);
                *(__nv_bfloat162*)&g_attn_bf[(size_t)(base + q0 + r0) * C_ + cc] = o;
            }
            if (r0 + 8 < Nq) {
                float iv = inv[r0 + 8];
                __nv_bfloat162 o = __floats2bfloat162_rn(acc[2] * iv, acc[3] * iv);
                *(__nv_bfloat162*)&g_attn_bf[(size_t)(base + q0 + r0 + 8) * C_ + cc] = o;
            }
        }

        // Q prefetch landed; fence S/Q reuse for next block
        asm volatile("cp.async.wait_group 0;");
        __syncthreads();
    }
}

// ---------------------------------------------------------------------------
// launch
// ---------------------------------------------------------------------------
extern "C" void kernel_launch(void* const* d_in, const int* in_sizes, int n_in,
                              void* d_out, int out_size)
{
    const float* x      = (const float*)d_in[0];
    const float* scale  = (const float*)d_in[1];
    const float* w_qkv  = (const float*)d_in[2];
    const float* w_proj = (const float*)d_in[3];
    const float* b_proj = (const float*)d_in[4];
    float* out = (float*)d_out;

    float *qkv_p;
    __nv_bfloat16 *attnbf_p, *xbf_p, *wqkvbf_p, *wprojbf_p;
    cudaGetSymbolAddress((void**)&qkv_p,    g_qkv);
    cudaGetSymbolAddress((void**)&attnbf_p, g_attn_bf);
    cudaGetSymbolAddress((void**)&xbf_p,    g_x_bf);
    cudaGetSymbolAddress((void**)&wqkvbf_p, g_wqkv_bf);
    cudaGetSymbolAddress((void**)&wprojbf_p, g_wproj_bf);

    const int smem_gemm = 2 * 2 * 128 * 36 * 4;        // 73728 B
    const int smem_attn = ATTN_SMEM_WORDS * 4;         // 150272 B
    cudaFuncSetAttribute(gemm_bf16<false>, cudaFuncAttributeMaxDynamicSharedMemorySize, smem_gemm);
    cudaFuncSetAttribute(gemm_bf16<true>,  cudaFuncAttributeMaxDynamicSharedMemorySize, smem_gemm);
    cudaFuncSetAttribute(attn_kernel,      cudaFuncAttributeMaxDynamicSharedMemorySize, smem_attn);

    // 0) convert inputs to bf16
    {
        int n4 = M_ * C_ / 4;
        cvt_bf16<<<(n4 + 255) / 256, 256>>>((const float4*)x, (uint2*)xbf_p, n4);
        n4 = O3_ * C_ / 4;
        cvt_bf16<<<(n4 + 255) / 256, 256>>>((const float4*)w_qkv, (uint2*)wqkvbf_p, n4);
        n4 = C_ * C_ / 4;
        cvt_bf16<<<(n4 + 255) / 256, 256>>>((const float4*)w_proj, (uint2*)wprojbf_p, n4);
    }

    // 1) QKV projection (bf16 in, fp32 out): [12608, 2304]
    gemm_bf16<false><<<dim3(O3_ / 128, (M_ + 127) / 128), 256, smem_gemm>>>(
        xbf_p, wqkvbf_p, qkv_p, M_, O3_, C_, nullptr, nullptr);

    // 2) fused masked attention: one CTA per (head, batch); writes bf16
    attn_kernel<<<dim3(H_, B_), 512, smem_attn>>>(scale);

    // 3) output projection + bias + residual (bf16 in, fp32 out)
    gemm_bf16<true><<<dim3(C_ / 128, (M_ + 127) / 128), 256, smem_gemm>>>(
        attnbf_p, wprojbf_p, out, M_, C_, C_, b_proj, x);
}